// round 9
// baseline (speedup 1.0000x reference)
#include <cuda_runtime.h>

#define B_   32
#define T_   512
#define NS_  32
#define H_   128
#define G_   512      // 4*H
#define KT_  160      // H + NS (h part then x part)
#define KS_  96       // smem-resident k rows
#define KR_  64       // register-resident k rows

// Transposed combined weights: Wt[n][k][r]; k<128 -> W_hh[n][r][k], else W_ih[n][r][k-128]
__device__ float g_Wt[(size_t)NS_ * KT_ * G_];

static __device__ __forceinline__ unsigned long long pk2(float x) {
    unsigned long long r;
    asm("mov.b64 %0, {%1, %1};" : "=l"(r) : "f"(x));
    return r;
}
static __device__ __forceinline__ void upk2(unsigned long long v, float& a, float& b) {
    asm("mov.b64 {%0, %1}, %2;" : "=f"(a), "=f"(b) : "l"(v));
}
static __device__ __forceinline__ unsigned long long ff2(unsigned long long a,
                                                         unsigned long long b,
                                                         unsigned long long c) {
    unsigned long long d;
    asm("fma.rn.f32x2 %0, %1, %2, %3;" : "=l"(d) : "l"(a), "l"(b), "l"(c));
    return d;
}
static __device__ __forceinline__ float sigm_(float x) {
    float e = __expf(-x);
    float r;
    asm("rcp.approx.f32 %0, %1;" : "=f"(r) : "f"(1.0f + e));
    return r;
}
static __device__ __forceinline__ float tanh_(float x) {
    return fmaf(2.0f, sigm_(2.0f * x), -1.0f);
}

// ---------------- prep: transpose weights into g_Wt (coalesced writes) ----
__global__ void prep_k(const float* __restrict__ Whh, const float* __restrict__ Wih) {
    const int k = blockIdx.x;        // 0..159
    const int n = blockIdx.y;        // 0..31
    const int r = threadIdx.x;       // 0..511
    float v;
    if (k < H_) v = Whh[((size_t)n * G_ + r) * H_ + k];
    else        v = Wih[((size_t)n * G_ + r) * NS_ + (k - H_)];
    g_Wt[((size_t)n * KT_ + k) * G_ + r] = v;
}

// ---------------- persistent LSTM kernel ----------------
// smem floats: sWs[96][512] | sv[160][8] | sg[512][12] | sred[64]  = 226560 B
#define SMEM_BYTES ((KS_*G_ + KT_*8 + G_*12 + 64) * 4)

__global__ __launch_bounds__(256, 1)
void lstm_k(const float* __restrict__ X,
            const float* __restrict__ bih,
            const float* __restrict__ bhh,
            const float* __restrict__ Wout,
            const float* __restrict__ bout,
            float* __restrict__ out) {
    extern __shared__ float sm[];
    float* sWs  = sm;                     // [KS_][512]
    float* sv   = sWs + KS_ * G_;         // [160][8] : rows 0..127 h, 128..159 x_t
    float* sg   = sv + KT_ * 8;           // [512][12] activated gate staging (padded)
    float* sred = sg + G_ * 12;           // [8 warps][8 batch] head partials

    const int tid = threadIdx.x;
    const int n   = blockIdx.x >> 2;
    const int b0  = (blockIdx.x & 3) * 8;
    const int r0  = tid * 2;             // this thread's first gate row
    const bool is_g = ((tid >> 6) == 2); // rows 256..383 are the g gate (tanh)

    // ---- cooperative load of smem weight slice (k in [0,96)) ----
    {
        const float4* src = (const float4*)(g_Wt + (size_t)n * KT_ * G_);
        float4* dst = (float4*)sWs;
        #pragma unroll
        for (int i = 0; i < (KS_ * G_ / 4) / 256; ++i)
            dst[tid + i * 256] = src[tid + i * 256];
    }
    // ---- register-resident weight slice (k in [96,160)) ----
    float wr[2 * KR_];
    {
        const float* ws = g_Wt + ((size_t)n * KT_ + KS_) * G_ + r0;
        #pragma unroll
        for (int kk = 0; kk < KR_; ++kk) {
            float2 w = *(const float2*)(ws + (size_t)kk * G_);
            wr[2 * kk]     = w.x;
            wr[2 * kk + 1] = w.y;
        }
    }
    const float bA = bih[n * G_ + r0]     + bhh[n * G_ + r0];
    const float bB = bih[n * G_ + r0 + 1] + bhh[n * G_ + r0 + 1];
    const float bo = bout[n];

    const int j  = tid >> 1;             // owned h index in update phase
    const int bq = (tid & 1) * 4;        // owned batch quartet
    const float swj = Wout[n * H_ + j];  // head weight for owned h index

    // ---- init h = 0, load x(0) ----
    for (int i = tid; i < H_ * 8; i += 256) sv[i] = 0.0f;
    {
        int b = tid >> 5, p = tid & 31;
        sv[(H_ + p) * 8 + b] = X[((size_t)(b0 + b) * T_ + 0) * NS_ + p];
    }
    float cq[4] = {0.f, 0.f, 0.f, 0.f};
    __syncthreads();

    for (int t = 0; t < T_; ++t) {
        // ---- Phase A: gates[r0..r0+1][8] over K=160 ----
        unsigned long long a00 = pk2(bA), a01 = a00, a02 = a00, a03 = a00;
        unsigned long long a10 = pk2(bB), a11 = a10, a12 = a10, a13 = a10;
        #pragma unroll 4
        for (int k = 0; k < KS_; ++k) {
            float2 w = *(const float2*)(sWs + k * G_ + r0);
            ulonglong2 vA = *(const ulonglong2*)(sv + k * 8);
            ulonglong2 vB = *(const ulonglong2*)(sv + k * 8 + 4);
            unsigned long long w0 = pk2(w.x), w1 = pk2(w.y);
            a00 = ff2(w0, vA.x, a00); a01 = ff2(w0, vA.y, a01);
            a02 = ff2(w0, vB.x, a02); a03 = ff2(w0, vB.y, a03);
            a10 = ff2(w1, vA.x, a10); a11 = ff2(w1, vA.y, a11);
            a12 = ff2(w1, vB.x, a12); a13 = ff2(w1, vB.y, a13);
        }
        #pragma unroll
        for (int kk = 0; kk < KR_; ++kk) {
            ulonglong2 vA = *(const ulonglong2*)(sv + (KS_ + kk) * 8);
            ulonglong2 vB = *(const ulonglong2*)(sv + (KS_ + kk) * 8 + 4);
            unsigned long long w0 = pk2(wr[2 * kk]), w1 = pk2(wr[2 * kk + 1]);
            a00 = ff2(w0, vA.x, a00); a01 = ff2(w0, vA.y, a01);
            a02 = ff2(w0, vB.x, a02); a03 = ff2(w0, vB.y, a03);
            a10 = ff2(w1, vA.x, a10); a11 = ff2(w1, vA.y, a11);
            a12 = ff2(w1, vB.x, a12); a13 = ff2(w1, vB.y, a13);
        }
        // ---- Phase B: activate + stage ----
        {
            float g0[8], g1[8];
            upk2(a00, g0[0], g0[1]); upk2(a01, g0[2], g0[3]);
            upk2(a02, g0[4], g0[5]); upk2(a03, g0[6], g0[7]);
            upk2(a10, g1[0], g1[1]); upk2(a11, g1[2], g1[3]);
            upk2(a12, g1[4], g1[5]); upk2(a13, g1[6], g1[7]);
            if (is_g) {
                #pragma unroll
                for (int b = 0; b < 8; b++) { g0[b] = tanh_(g0[b]); g1[b] = tanh_(g1[b]); }
            } else {
                #pragma unroll
                for (int b = 0; b < 8; b++) { g0[b] = sigm_(g0[b]); g1[b] = sigm_(g1[b]); }
            }
            *(float4*)(sg + (size_t)r0 * 12)           = make_float4(g0[0], g0[1], g0[2], g0[3]);
            *(float4*)(sg + (size_t)r0 * 12 + 4)       = make_float4(g0[4], g0[5], g0[6], g0[7]);
            *(float4*)(sg + (size_t)(r0 + 1) * 12)     = make_float4(g1[0], g1[1], g1[2], g1[3]);
            *(float4*)(sg + (size_t)(r0 + 1) * 12 + 4) = make_float4(g1[4], g1[5], g1[6], g1[7]);
        }
        __syncthreads();
        // ---- Phase C: c/h update (thread owns (j, bq..bq+3)) + head partials ----
        {
            float4 gi = *(const float4*)(sg + (size_t)j * 12 + bq);
            float4 gf = *(const float4*)(sg + (size_t)(H_ + j) * 12 + bq);
            float4 gg = *(const float4*)(sg + (size_t)(2 * H_ + j) * 12 + bq);
            float4 go = *(const float4*)(sg + (size_t)(3 * H_ + j) * 12 + bq);
            float iv[4] = {gi.x, gi.y, gi.z, gi.w};
            float fv[4] = {gf.x, gf.y, gf.z, gf.w};
            float gv[4] = {gg.x, gg.y, gg.z, gg.w};
            float ov[4] = {go.x, go.y, go.z, go.w};
            float hq[4], pp[4];
            #pragma unroll
            for (int q = 0; q < 4; q++) {
                cq[q] = fv[q] * cq[q] + iv[q] * gv[q];
                hq[q] = ov[q] * tanh_(cq[q]);
                pp[q] = hq[q] * swj;
            }
            *(float4*)(sv + (size_t)j * 8 + bq) = make_float4(hq[0], hq[1], hq[2], hq[3]);
            // warp reduce over same-parity lanes (16 distinct j per parity group)
            #pragma unroll
            for (int m = 2; m <= 16; m <<= 1) {
                pp[0] += __shfl_xor_sync(0xffffffffu, pp[0], m);
                pp[1] += __shfl_xor_sync(0xffffffffu, pp[1], m);
                pp[2] += __shfl_xor_sync(0xffffffffu, pp[2], m);
                pp[3] += __shfl_xor_sync(0xffffffffu, pp[3], m);
            }
            if ((tid & 31) < 2) {
                int w = tid >> 5;   // lane 0 -> batches 0..3 (bq=0), lane 1 -> 4..7 (bq=4)
                *(float4*)(sred + w * 8 + bq) = make_float4(pp[0], pp[1], pp[2], pp[3]);
            }
        }
        // next x_t
        if (t + 1 < T_) {
            int b = tid >> 5, p = tid & 31;
            sv[(H_ + p) * 8 + b] = X[((size_t)(b0 + b) * T_ + (t + 1)) * NS_ + p];
        }
        __syncthreads();
        // ---- head finish: 8 threads sum the per-warp partials ----
        if (tid < 8) {
            float s = bo;
            #pragma unroll
            for (int w = 0; w < 8; w++) s += sred[w * 8 + tid];
            out[((size_t)(b0 + tid) * T_ + t) * NS_ + n] = s;
        }
    }

    // ---- final hT, cT: [N,B,H] each, after pred block ----
    {
        const size_t OB  = (size_t)B_ * T_ * NS_;
        const size_t OC  = OB + (size_t)NS_ * B_ * H_;
        #pragma unroll
        for (int q = 0; q < 4; q++) {
            int b = b0 + bq + q;
            out[OB + ((size_t)n * B_ + b) * H_ + j] = sv[(size_t)j * 8 + bq + q];
            out[OC + ((size_t)n * B_ + b) * H_ + j] = cq[q];
        }
    }
}

extern "C" void kernel_launch(void* const* d_in, const int* in_sizes, int n_in,
                              void* d_out, int out_size) {
    const float* X    = (const float*)d_in[0];
    const float* Wih  = (const float*)d_in[1];
    const float* Whh  = (const float*)d_in[2];
    const float* bih  = (const float*)d_in[3];
    const float* bhh  = (const float*)d_in[4];
    const float* Wout = (const float*)d_in[5];
    const float* bout = (const float*)d_in[6];
    float* out = (float*)d_out;

    prep_k<<<dim3(KT_, NS_), G_>>>(Whh, Wih);

    cudaFuncSetAttribute(lstm_k, cudaFuncAttributeMaxDynamicSharedMemorySize, SMEM_BYTES);
    lstm_k<<<NS_ * 4, 256, SMEM_BYTES>>>(X, bih, bhh, Wout, bout, out);
}

// round 11
// speedup vs baseline: 1.0075x; 1.0075x over previous
#include <cuda_runtime.h>
#include <cstdint>

#define B_   32
#define T_   512
#define NS_  32
#define H_   128
#define G_   512      // 4*H
#define KT_  160      // H + NS (h rows then x rows)
#define KS_  88       // smem-resident k rows total
#define KGS_ 44       // smem k rows per group
#define KRG_ 36       // register k rows per group  (88 + 2*36 = 160)

// Transposed combined weights: Wt[n][k][r]; k<128 -> W_hh[n][r][k], else W_ih[n][r][k-128]
__device__ float g_Wt[(size_t)NS_ * KT_ * G_];

static __device__ __forceinline__ unsigned long long pk2(float x) {
    unsigned long long r;
    asm("mov.b64 %0, {%1, %1};" : "=l"(r) : "f"(x));
    return r;
}
static __device__ __forceinline__ void upk2(unsigned long long v, float& a, float& b) {
    asm("mov.b64 {%0, %1}, %2;" : "=f"(a), "=f"(b) : "l"(v));
}
static __device__ __forceinline__ unsigned long long ff2(unsigned long long a,
                                                         unsigned long long b,
                                                         unsigned long long c) {
    unsigned long long d;
    asm("fma.rn.f32x2 %0, %1, %2, %3;" : "=l"(d) : "l"(a), "l"(b), "l"(c));
    return d;
}
static __device__ __forceinline__ float sigm_(float x) {
    float e = __expf(-x);
    float r;
    asm("rcp.approx.f32 %0, %1;" : "=f"(r) : "f"(1.0f + e));
    return r;
}
static __device__ __forceinline__ float tanh_(float x) {
    return fmaf(2.0f, sigm_(2.0f * x), -1.0f);
}

// ---------------- prep: transpose weights into g_Wt (coalesced writes) ----
__global__ void prep_k(const float* __restrict__ Whh, const float* __restrict__ Wih) {
    const int k = blockIdx.x;        // 0..159
    const int n = blockIdx.y;        // 0..31
    const int r = threadIdx.x;       // 0..511
    float v;
    if (k < H_) v = Whh[((size_t)n * G_ + r) * H_ + k];
    else        v = Wih[((size_t)n * G_ + r) * NS_ + (k - H_)];
    g_Wt[((size_t)n * KT_ + k) * G_ + r] = v;
}

// ---------------- persistent LSTM kernel, 512 threads, k-split ----------------
// smem floats: sWs[88][512] | sv[160][8] | sg[512][12] | sred[64] | sp[4][512] u64
#define SW_F (KS_ * G_)
#define SV_F (KT_ * 8)
#define SG_F (G_ * 12)
#define SMEM_BYTES ((SW_F + SV_F + SG_F + 64 + G_ * 8) * 4)

__global__ __launch_bounds__(512, 1)
void lstm_k(const float* __restrict__ X,
            const float* __restrict__ bih,
            const float* __restrict__ bhh,
            const float* __restrict__ Wout,
            const float* __restrict__ bout,
            float* __restrict__ out) {
    extern __shared__ float sm[];
    float* sWs  = sm;                     // [KS_][512]
    float* sv   = sWs + SW_F;             // [160][8] : rows 0..127 h, 128..159 x_t
    float* sg   = sv + SV_F;              // [512][12] activated gate staging
    float* sred = sg + SG_F;              // [8 warps][8 batch] head partials
    unsigned long long* spu = (unsigned long long*)(sred + 64);  // [4 bpair][512 r]

    const int tid = threadIdx.x;
    const int gid = tid >> 8;            // k-group: 0 or 1
    const int tm  = tid & 255;
    const int r0  = tm * 2;              // this thread's first gate row
    const int n   = blockIdx.x >> 2;
    const int b0  = (blockIdx.x & 3) * 8;
    const bool is_g = ((tm >> 6) == 2);  // rows 256..383 are the g gate (tanh)

    // ---- cooperative load of smem weight slice (k in [0,88)) ----
    {
        const float4* src = (const float4*)(g_Wt + (size_t)n * KT_ * G_);
        float4* dst = (float4*)sWs;
        #pragma unroll
        for (int i = 0; i < (SW_F / 4) / 512; ++i)
            dst[tid + i * 512] = src[tid + i * 512];
    }
    // ---- register-resident weight slice: rows [88+gid*36, 88+gid*36+36) ----
    float wr[2 * KRG_];
    {
        const float* ws = g_Wt + ((size_t)n * KT_ + KS_ + gid * KRG_) * G_ + r0;
        #pragma unroll
        for (int kk = 0; kk < KRG_; ++kk) {
            float2 w = *(const float2*)(ws + (size_t)kk * G_);
            wr[2 * kk]     = w.x;
            wr[2 * kk + 1] = w.y;
        }
    }
    const float bA = (gid == 0) ? (bih[n * G_ + r0]     + bhh[n * G_ + r0])     : 0.0f;
    const float bB = (gid == 0) ? (bih[n * G_ + r0 + 1] + bhh[n * G_ + r0 + 1]) : 0.0f;
    const float bo = bout[n];

    const int j  = tm >> 1;              // owned h index in update phase (group 0)
    const int bq = (tm & 1) * 4;         // owned batch quartet
    const float swj = (gid == 0) ? Wout[n * H_ + j] : 0.0f;

    // ---- init h = 0, load x(0) ----
    for (int i = tid; i < H_ * 8; i += 512) sv[i] = 0.0f;
    if (gid == 0) {
        int b = tm >> 5, p = tm & 31;
        sv[(H_ + p) * 8 + b] = X[((size_t)(b0 + b) * T_ + 0) * NS_ + p];
    }
    float cq[4] = {0.f, 0.f, 0.f, 0.f};
    const int ksm0 = gid * KGS_;         // smem k range base
    const int krg0 = KS_ + gid * KRG_;   // reg k range base (sv row index)
    const unsigned long long one2 = pk2(1.0f);
    __syncthreads();

    for (int t = 0; t < T_; ++t) {
        // ---- Phase A: partial gates[r0..r0+1][8] over this group's 80 k ----
        unsigned long long a00 = pk2(bA), a01 = a00, a02 = a00, a03 = a00;
        unsigned long long a10 = pk2(bB), a11 = a10, a12 = a10, a13 = a10;
        #pragma unroll 4
        for (int k = 0; k < KGS_; ++k) {
            float2 w = *(const float2*)(sWs + (ksm0 + k) * G_ + r0);
            ulonglong2 vA = *(const ulonglong2*)(sv + (ksm0 + k) * 8);
            ulonglong2 vB = *(const ulonglong2*)(sv + (ksm0 + k) * 8 + 4);
            unsigned long long w0 = pk2(w.x), w1 = pk2(w.y);
            a00 = ff2(w0, vA.x, a00); a01 = ff2(w0, vA.y, a01);
            a02 = ff2(w0, vB.x, a02); a03 = ff2(w0, vB.y, a03);
            a10 = ff2(w1, vA.x, a10); a11 = ff2(w1, vA.y, a11);
            a12 = ff2(w1, vB.x, a12); a13 = ff2(w1, vB.y, a13);
        }
        #pragma unroll
        for (int kk = 0; kk < KRG_; ++kk) {
            ulonglong2 vA = *(const ulonglong2*)(sv + (krg0 + kk) * 8);
            ulonglong2 vB = *(const ulonglong2*)(sv + (krg0 + kk) * 8 + 4);
            unsigned long long w0 = pk2(wr[2 * kk]), w1 = pk2(wr[2 * kk + 1]);
            a00 = ff2(w0, vA.x, a00); a01 = ff2(w0, vA.y, a01);
            a02 = ff2(w0, vB.x, a02); a03 = ff2(w0, vB.y, a03);
            a10 = ff2(w1, vA.x, a10); a11 = ff2(w1, vA.y, a11);
            a12 = ff2(w1, vB.x, a12); a13 = ff2(w1, vB.y, a13);
        }
        // group 1 publishes partials
        if (gid == 1) {
            spu[0 * G_ + r0]     = a00;
            spu[1 * G_ + r0]     = a01;
            spu[2 * G_ + r0]     = a02;
            spu[3 * G_ + r0]     = a03;
            spu[0 * G_ + r0 + 1] = a10;
            spu[1 * G_ + r0 + 1] = a11;
            spu[2 * G_ + r0 + 1] = a12;
            spu[3 * G_ + r0 + 1] = a13;
        }
        __syncthreads();
        // ---- Phase B: group 0 combines + activates + stages; group 1 loads x(t+1) ----
        if (gid == 0) {
            a00 = ff2(one2, spu[0 * G_ + r0],     a00);
            a01 = ff2(one2, spu[1 * G_ + r0],     a01);
            a02 = ff2(one2, spu[2 * G_ + r0],     a02);
            a03 = ff2(one2, spu[3 * G_ + r0],     a03);
            a10 = ff2(one2, spu[0 * G_ + r0 + 1], a10);
            a11 = ff2(one2, spu[1 * G_ + r0 + 1], a11);
            a12 = ff2(one2, spu[2 * G_ + r0 + 1], a12);
            a13 = ff2(one2, spu[3 * G_ + r0 + 1], a13);
            float g0[8], g1[8];
            upk2(a00, g0[0], g0[1]); upk2(a01, g0[2], g0[3]);
            upk2(a02, g0[4], g0[5]); upk2(a03, g0[6], g0[7]);
            upk2(a10, g1[0], g1[1]); upk2(a11, g1[2], g1[3]);
            upk2(a12, g1[4], g1[5]); upk2(a13, g1[6], g1[7]);
            if (is_g) {
                #pragma unroll
                for (int b = 0; b < 8; b++) { g0[b] = tanh_(g0[b]); g1[b] = tanh_(g1[b]); }
            } else {
                #pragma unroll
                for (int b = 0; b < 8; b++) { g0[b] = sigm_(g0[b]); g1[b] = sigm_(g1[b]); }
            }
            *(float4*)(sg + (size_t)r0 * 12)           = make_float4(g0[0], g0[1], g0[2], g0[3]);
            *(float4*)(sg + (size_t)r0 * 12 + 4)       = make_float4(g0[4], g0[5], g0[6], g0[7]);
            *(float4*)(sg + (size_t)(r0 + 1) * 12)     = make_float4(g1[0], g1[1], g1[2], g1[3]);
            *(float4*)(sg + (size_t)(r0 + 1) * 12 + 4) = make_float4(g1[4], g1[5], g1[6], g1[7]);
        } else if (t + 1 < T_) {
            int b = tm >> 5, p = tm & 31;
            sv[(H_ + p) * 8 + b] = X[((size_t)(b0 + b) * T_ + (t + 1)) * NS_ + p];
        }
        __syncthreads();
        // ---- Phase C: group 0 does c/h update + head partials ----
        if (gid == 0) {
            float4 gi = *(const float4*)(sg + (size_t)j * 12 + bq);
            float4 gf = *(const float4*)(sg + (size_t)(H_ + j) * 12 + bq);
            float4 gg = *(const float4*)(sg + (size_t)(2 * H_ + j) * 12 + bq);
            float4 go = *(const float4*)(sg + (size_t)(3 * H_ + j) * 12 + bq);
            float iv[4] = {gi.x, gi.y, gi.z, gi.w};
            float fv[4] = {gf.x, gf.y, gf.z, gf.w};
            float gv[4] = {gg.x, gg.y, gg.z, gg.w};
            float ov[4] = {go.x, go.y, go.z, go.w};
            float hq[4], pp[4];
            #pragma unroll
            for (int q = 0; q < 4; q++) {
                cq[q] = fv[q] * cq[q] + iv[q] * gv[q];
                hq[q] = ov[q] * tanh_(cq[q]);
                pp[q] = hq[q] * swj;
            }
            *(float4*)(sv + (size_t)j * 8 + bq) = make_float4(hq[0], hq[1], hq[2], hq[3]);
            #pragma unroll
            for (int m = 2; m <= 16; m <<= 1) {
                pp[0] += __shfl_xor_sync(0xffffffffu, pp[0], m);
                pp[1] += __shfl_xor_sync(0xffffffffu, pp[1], m);
                pp[2] += __shfl_xor_sync(0xffffffffu, pp[2], m);
                pp[3] += __shfl_xor_sync(0xffffffffu, pp[3], m);
            }
            if ((tm & 31) < 2) {
                int w = tm >> 5;   // lane 0 -> batches 0..3, lane 1 -> 4..7
                *(float4*)(sred + w * 8 + bq) = make_float4(pp[0], pp[1], pp[2], pp[3]);
            }
        }
        __syncthreads();
        // ---- head finish: 8 threads sum the per-warp partials ----
        if (tid < 8) {
            float s = bo;
            #pragma unroll
            for (int w = 0; w < 8; w++) s += sred[w * 8 + tid];
            out[((size_t)(b0 + tid) * T_ + t) * NS_ + n] = s;
        }
    }

    // ---- final hT, cT: [N,B,H] each, after pred block ----
    if (gid == 0) {
        const size_t OB = (size_t)B_ * T_ * NS_;
        const size_t OC = OB + (size_t)NS_ * B_ * H_;
        #pragma unroll
        for (int q = 0; q < 4; q++) {
            int b = b0 + bq + q;
            out[OB + ((size_t)n * B_ + b) * H_ + j] = sv[(size_t)j * 8 + bq + q];
            out[OC + ((size_t)n * B_ + b) * H_ + j] = cq[q];
        }
    }
}

extern "C" void kernel_launch(void* const* d_in, const int* in_sizes, int n_in,
                              void* d_out, int out_size) {
    const float* X    = (const float*)d_in[0];
    const float* Wih  = (const float*)d_in[1];
    const float* Whh  = (const float*)d_in[2];
    const float* bih  = (const float*)d_in[3];
    const float* bhh  = (const float*)d_in[4];
    const float* Wout = (const float*)d_in[5];
    const float* bout = (const float*)d_in[6];
    float* out = (float*)d_out;

    prep_k<<<dim3(KT_, NS_), G_>>>(Whh, Wih);

    cudaFuncSetAttribute(lstm_k, cudaFuncAttributeMaxDynamicSharedMemorySize, SMEM_BYTES);
    lstm_k<<<NS_ * 4, 512, SMEM_BYTES>>>(X, bih, bhh, Wout, bout, out);
}

// round 12
// speedup vs baseline: 1.1022x; 1.0940x over previous
#include <cuda_runtime.h>
#include <cstdint>

#define B_   32
#define T_   512
#define NS_  32
#define H_   128
#define G_   512      // 4*H
#define KT_  160      // H + NS (h rows then x rows)
#define KS_  96       // smem-resident k rows (48 per group)
#define KRG_ 32       // register k rows per group

// Permuted transposed weights: Wt[n][k][r'], r' = 4*j + gate, gate in {i,f,g,o}
__device__ float g_Wt[(size_t)NS_ * KT_ * G_];

static __device__ __forceinline__ unsigned long long pk2(float x) {
    unsigned long long r;
    asm("mov.b64 %0, {%1, %1};" : "=l"(r) : "f"(x));
    return r;
}
static __device__ __forceinline__ void upk2(unsigned long long v, float& a, float& b) {
    asm("mov.b64 {%0, %1}, %2;" : "=f"(a), "=f"(b) : "l"(v));
}
static __device__ __forceinline__ unsigned long long ff2(unsigned long long a,
                                                         unsigned long long b,
                                                         unsigned long long c) {
    unsigned long long d;
    asm("fma.rn.f32x2 %0, %1, %2, %3;" : "=l"(d) : "l"(a), "l"(b), "l"(c));
    return d;
}
static __device__ __forceinline__ float sigm_(float x) {
    float e = __expf(-x);
    float r;
    asm("rcp.approx.f32 %0, %1;" : "=f"(r) : "f"(1.0f + e));
    return r;
}
static __device__ __forceinline__ float tanh_(float x) {
    return fmaf(2.0f, sigm_(2.0f * x), -1.0f);
}

// ---------------- prep: permuted transpose (r' = 4j + gate) ----------------
__global__ void prep_k(const float* __restrict__ Whh, const float* __restrict__ Wih) {
    const int k  = blockIdx.x;       // 0..159
    const int n  = blockIdx.y;       // 0..31
    const int rp = threadIdx.x;      // 0..511 permuted row
    const int j  = rp >> 2, g = rp & 3;
    const int orow = g * H_ + j;     // original gate row
    float v;
    if (k < H_) v = Whh[((size_t)n * G_ + orow) * H_ + k];
    else        v = Wih[((size_t)n * G_ + orow) * NS_ + (k - H_)];
    g_Wt[((size_t)n * KT_ + k) * G_ + rp] = v;
}

// ---------------- persistent LSTM kernel ----------------
// smem floats: sWs[96][512] | sv[160][8] | spu[16][256] | sred[8][4]
#define SW_F  (KS_ * G_)
#define SV_F  (KT_ * 8)
#define SPU_F (16 * 256)
#define SMEM_BYTES ((SW_F + SV_F + SPU_F + 32) * 4)

__global__ __launch_bounds__(256, 1)
void lstm_k(const float* __restrict__ X,
            const float* __restrict__ bih,
            const float* __restrict__ bhh,
            const float* __restrict__ Wout,
            const float* __restrict__ bout,
            float* __restrict__ out) {
    extern __shared__ float sm[];
    float* sWs  = sm;                 // [96][512]
    float* sv   = sWs + SW_F;         // [160][8] rows 0..127 h, 128..159 x
    float* spu  = sv + SV_F;          // [16][256] partial exchange
    float* sred = spu + SPU_F;        // [8 warps][4] head partials

    const int tid = threadIdx.x;
    const int wid = tid >> 5, lid = tid & 31;
    const int tm  = tid & 127;        // owned h-index j
    const int kg  = tid >> 7;         // k-group 0/1
    const int n   = blockIdx.x >> 2;
    const int b0  = (blockIdx.x & 3) * 8;
    const int ptid = tid ^ 128;       // peer thread slot

    // ---- cooperative load of all 96 smem weight rows ----
    {
        const float4* src = (const float4*)(g_Wt + (size_t)n * KT_ * G_);
        float4* dst = (float4*)sWs;
        #pragma unroll
        for (int i = 0; i < (SW_F / 4) / 256; ++i)
            dst[tid + i * 256] = src[tid + i * 256];
    }
    // ---- register weight rows: kg0 -> k 96..127, kg1 -> k 128..159 ----
    float wr[4 * KRG_];
    {
        const float* ws = g_Wt + ((size_t)n * KT_ + KS_ + kg * KRG_) * G_ + 4 * tm;
        #pragma unroll
        for (int kk = 0; kk < KRG_; ++kk) {
            float4 w = *(const float4*)(ws + (size_t)kk * G_);
            wr[4 * kk]     = w.x;
            wr[4 * kk + 1] = w.y;
            wr[4 * kk + 2] = w.z;
            wr[4 * kk + 3] = w.w;
        }
    }
    // ---- biases (kg0 only), head weight ----
    float bias[4];
    #pragma unroll
    for (int g = 0; g < 4; ++g)
        bias[g] = (kg == 0) ? (bih[n * G_ + g * H_ + tm] + bhh[n * G_ + g * H_ + tm]) : 0.0f;
    const float wo = Wout[n * H_ + tm];
    const float bo = bout[n];

    // ---- init h = 0, load x(0) ----
    for (int i = tid; i < H_ * 8; i += 256) sv[i] = 0.0f;
    {
        int b = tid >> 5, p = tid & 31;
        sv[(H_ + p) * 8 + b] = X[((size_t)(b0 + b) * T_ + 0) * NS_ + p];
    }
    float c4[4] = {0.f, 0.f, 0.f, 0.f};
    float h4[4] = {0.f, 0.f, 0.f, 0.f};
    const int ksm0 = kg * 48;
    const int oo   = 2 * (1 - kg);    // acc u64 cols to send (other batch-half)
    const int mo   = 2 * kg;          // acc u64 cols to keep
    __syncthreads();

    for (int t = 0; t < T_; ++t) {
        // x(t+1) prefetch (gmem, long latency — issue first)
        float xv = 0.0f;
        if (t + 1 < T_)
            xv = X[((size_t)(b0 + (tid >> 5)) * T_ + (t + 1)) * NS_ + (tid & 31)];

        // ---- Phase A: acc[gate][bpair] over this group's 80 k ----
        unsigned long long a[4][4];
        #pragma unroll
        for (int g = 0; g < 4; ++g) {
            unsigned long long bb = pk2(bias[g]);
            a[g][0] = bb; a[g][1] = bb; a[g][2] = bb; a[g][3] = bb;
        }
        #pragma unroll 4
        for (int k = 0; k < 48; ++k) {
            const int ks = ksm0 + k;
            float4 w = *(const float4*)(sWs + ks * G_ + 4 * tm);
            ulonglong2 vA = *(const ulonglong2*)(sv + ks * 8);
            ulonglong2 vB = *(const ulonglong2*)(sv + ks * 8 + 4);
            unsigned long long w0 = pk2(w.x), w1 = pk2(w.y), w2 = pk2(w.z), w3 = pk2(w.w);
            a[0][0] = ff2(w0, vA.x, a[0][0]); a[0][1] = ff2(w0, vA.y, a[0][1]);
            a[0][2] = ff2(w0, vB.x, a[0][2]); a[0][3] = ff2(w0, vB.y, a[0][3]);
            a[1][0] = ff2(w1, vA.x, a[1][0]); a[1][1] = ff2(w1, vA.y, a[1][1]);
            a[1][2] = ff2(w1, vB.x, a[1][2]); a[1][3] = ff2(w1, vB.y, a[1][3]);
            a[2][0] = ff2(w2, vA.x, a[2][0]); a[2][1] = ff2(w2, vA.y, a[2][1]);
            a[2][2] = ff2(w2, vB.x, a[2][2]); a[2][3] = ff2(w2, vB.y, a[2][3]);
            a[3][0] = ff2(w3, vA.x, a[3][0]); a[3][1] = ff2(w3, vA.y, a[3][1]);
            a[3][2] = ff2(w3, vB.x, a[3][2]); a[3][3] = ff2(w3, vB.y, a[3][3]);
        }
        #pragma unroll
        for (int kk = 0; kk < KRG_; ++kk) {
            const int kr = KS_ + kg * KRG_ + kk;
            ulonglong2 vA = *(const ulonglong2*)(sv + kr * 8);
            ulonglong2 vB = *(const ulonglong2*)(sv + kr * 8 + 4);
            unsigned long long w0 = pk2(wr[4 * kk]),     w1 = pk2(wr[4 * kk + 1]);
            unsigned long long w2 = pk2(wr[4 * kk + 2]), w3 = pk2(wr[4 * kk + 3]);
            a[0][0] = ff2(w0, vA.x, a[0][0]); a[0][1] = ff2(w0, vA.y, a[0][1]);
            a[0][2] = ff2(w0, vB.x, a[0][2]); a[0][3] = ff2(w0, vB.y, a[0][3]);
            a[1][0] = ff2(w1, vA.x, a[1][0]); a[1][1] = ff2(w1, vA.y, a[1][1]);
            a[1][2] = ff2(w1, vB.x, a[1][2]); a[1][3] = ff2(w1, vB.y, a[1][3]);
            a[2][0] = ff2(w2, vA.x, a[2][0]); a[2][1] = ff2(w2, vA.y, a[2][1]);
            a[2][2] = ff2(w2, vB.x, a[2][2]); a[2][3] = ff2(w2, vB.y, a[2][3]);
            a[3][0] = ff2(w3, vA.x, a[3][0]); a[3][1] = ff2(w3, vA.y, a[3][1]);
            a[3][2] = ff2(w3, vB.x, a[3][2]); a[3][3] = ff2(w3, vB.y, a[3][3]);
        }
        // ---- publish other batch-half to peer (column layout, conflict-free) ----
        #pragma unroll
        for (int g = 0; g < 4; ++g) {
            float p0, p1, p2, p3;
            upk2(a[g][oo],     p0, p1);
            upk2(a[g][oo + 1], p2, p3);
            spu[(g * 4 + 0) * 256 + ptid] = p0;
            spu[(g * 4 + 1) * 256 + ptid] = p1;
            spu[(g * 4 + 2) * 256 + ptid] = p2;
            spu[(g * 4 + 3) * 256 + ptid] = p3;
        }
        __syncthreads();
        // ---- epilogue: combine, activate, c/h update, stores (no staging) ----
        {
            // x(t+1) into sv (phase A reads of x(t) are all complete)
            if (t + 1 < T_)
                sv[(H_ + (tid & 31)) * 8 + (tid >> 5)] = xv;

            float Gv[4][4];
            #pragma unroll
            for (int g = 0; g < 4; ++g) {
                float p0, p1, p2, p3;
                upk2(a[g][mo],     p0, p1);
                upk2(a[g][mo + 1], p2, p3);
                Gv[g][0] = p0 + spu[(g * 4 + 0) * 256 + tid];
                Gv[g][1] = p1 + spu[(g * 4 + 1) * 256 + tid];
                Gv[g][2] = p2 + spu[(g * 4 + 2) * 256 + tid];
                Gv[g][3] = p3 + spu[(g * 4 + 3) * 256 + tid];
            }
            float pp[4];
            #pragma unroll
            for (int q = 0; q < 4; ++q) {
                float iv = sigm_(Gv[0][q]);
                float fv = sigm_(Gv[1][q]);
                float gv = tanh_(Gv[2][q]);
                float ov = sigm_(Gv[3][q]);
                c4[q] = fv * c4[q] + iv * gv;
                h4[q] = ov * tanh_(c4[q]);
                pp[q] = h4[q] * wo;
            }
            *(float4*)(sv + tm * 8 + kg * 4) = make_float4(h4[0], h4[1], h4[2], h4[3]);
            // head: reduce 32 j's per warp
            #pragma unroll
            for (int m = 1; m <= 16; m <<= 1) {
                pp[0] += __shfl_xor_sync(0xffffffffu, pp[0], m);
                pp[1] += __shfl_xor_sync(0xffffffffu, pp[1], m);
                pp[2] += __shfl_xor_sync(0xffffffffu, pp[2], m);
                pp[3] += __shfl_xor_sync(0xffffffffu, pp[3], m);
            }
            if (lid == 0)
                *(float4*)(sred + wid * 4) = make_float4(pp[0], pp[1], pp[2], pp[3]);
        }
        __syncthreads();
        // ---- head finish: warps 0-3 hold b0-3, warps 4-7 hold b4-7 ----
        if (tid < 8) {
            const int kgb = tid >> 2, q = tid & 3;
            float s = bo;
            #pragma unroll
            for (int w = 0; w < 4; ++w) s += sred[(kgb * 4 + w) * 4 + q];
            out[((size_t)(b0 + tid) * T_ + t) * NS_ + n] = s;
        }
    }

    // ---- final hT, cT: [N,B,H] each, after pred block ----
    {
        const size_t OB = (size_t)B_ * T_ * NS_;
        const size_t OC = OB + (size_t)NS_ * B_ * H_;
        #pragma unroll
        for (int q = 0; q < 4; ++q) {
            int b = b0 + kg * 4 + q;
            out[OB + ((size_t)n * B_ + b) * H_ + tm] = h4[q];
            out[OC + ((size_t)n * B_ + b) * H_ + tm] = c4[q];
        }
    }
}

extern "C" void kernel_launch(void* const* d_in, const int* in_sizes, int n_in,
                              void* d_out, int out_size) {
    const float* X    = (const float*)d_in[0];
    const float* Wih  = (const float*)d_in[1];
    const float* Whh  = (const float*)d_in[2];
    const float* bih  = (const float*)d_in[3];
    const float* bhh  = (const float*)d_in[4];
    const float* Wout = (const float*)d_in[5];
    const float* bout = (const float*)d_in[6];
    float* out = (float*)d_out;

    prep_k<<<dim3(KT_, NS_), G_>>>(Whh, Wih);

    cudaFuncSetAttribute(lstm_k, cudaFuncAttributeMaxDynamicSharedMemorySize, SMEM_BYTES);
    lstm_k<<<NS_ * 4, 256, SMEM_BYTES>>>(X, bih, bhh, Wout, bout, out);
}

// round 13
// speedup vs baseline: 1.8006x; 1.6337x over previous
#include <cuda_runtime.h>
#include <cuda_bf16.h>
#include <cstdint>

#define T_  512
#define NS_ 32
#define H_  128

// Pre-fragmented weights: [ (n*2+jh) ][ frag f = mt*20 + part*10 + kc ][ lane ] -> uint4 (a0..a3)
__device__ uint4 g_W[(size_t)64 * 320 * 32];

// ---- smem layout (bytes) ----
#define SW_OFF   0          // 320 frags * 32 lanes * 16 B = 163840
#define V_OFF    163840     // 2 bufs * (hi 7680 + lo 7680) = 30720 ; row=24 u32, 80 rows
#define SD_OFF   194560     // 256 * 18 f32 = 18432
#define SRED_OFF 212992     // [buf][rank][16] f32 = 256
#define SMEM_BYTES 213248

static __device__ __forceinline__ uint32_t s2u(const void* p) {
    uint32_t a;
    asm("{ .reg .u64 t; cvta.to.shared.u64 t, %1; cvt.u32.u64 %0, t; }" : "=r"(a) : "l"(p));
    return a;
}
static __device__ __forceinline__ uint32_t mapa_(uint32_t a, uint32_t r) {
    uint32_t o;
    asm("mapa.shared::cluster.u32 %0, %1, %2;" : "=r"(o) : "r"(a), "r"(r));
    return o;
}
static __device__ __forceinline__ void stc64(uint32_t a, unsigned long long v) {
    asm volatile("st.shared::cluster.b64 [%0], %1;" :: "r"(a), "l"(v) : "memory");
}
static __device__ __forceinline__ float sigm_(float x) {
    float e = __expf(-x), r;
    asm("rcp.approx.f32 %0, %1;" : "=f"(r) : "f"(1.0f + e));
    return r;
}
static __device__ __forceinline__ float tanh_(float x) {
    return fmaf(2.0f, sigm_(2.0f * x), -1.0f);
}
#define MMA(D, A, B0, B1) asm volatile( \
    "mma.sync.aligned.m16n8k16.row.col.f32.bf16.bf16.f32 " \
    "{%0,%1,%2,%3}, {%4,%5,%6,%7}, {%8,%9}, {%0,%1,%2,%3};" \
    : "+f"((D)[0]), "+f"((D)[1]), "+f"((D)[2]), "+f"((D)[3]) \
    : "r"((A).x), "r"((A).y), "r"((A).z), "r"((A).w), "r"(B0), "r"(B1))
#define CSYNC() do { asm volatile("barrier.cluster.arrive.aligned;" ::: "memory"); \
                     asm volatile("barrier.cluster.wait.aligned;" ::: "memory"); } while (0)

// ---------------- prep: weights -> per-lane mma fragments, bf16 hi/lo ----------------
__global__ void prep_k(const float* __restrict__ Whh, const float* __restrict__ Wih) {
    const int nb = blockIdx.y;                 // n*2 + jh
    const int n = nb >> 1, jh = nb & 1;
    const int f = blockIdx.x;                  // mt*20 + part*10 + kc
    const int mt = f / 20, rem = f % 20, part = rem / 10, kc = rem % 10;
    const int l = threadIdx.x, gid = l >> 2, tid4 = l & 3;

    auto bits = [&](int r, int k) -> uint32_t {
        int g = r >> 6, jj = r & 63;
        int grow = g * 128 + jh * 64 + jj;
        float w = (k < 128) ? Whh[((size_t)n * 512 + grow) * 128 + k]
                            : Wih[((size_t)n * 512 + grow) * 32 + (k - 128)];
        __nv_bfloat16 hi = __float2bfloat16(w);
        __nv_bfloat16 v  = part ? __float2bfloat16(w - __bfloat162float(hi)) : hi;
        return (uint32_t)__bfloat16_as_ushort(v);
    };
    const int r0 = mt * 16 + gid, r1 = r0 + 8;
    const int k0 = kc * 16 + tid4 * 2, k2 = k0 + 8;
    uint4 frag;
    frag.x = bits(r0, k0) | (bits(r0, k0 + 1) << 16);
    frag.y = bits(r1, k0) | (bits(r1, k0 + 1) << 16);
    frag.z = bits(r0, k2) | (bits(r0, k2 + 1) << 16);
    frag.w = bits(r1, k2) | (bits(r1, k2 + 1) << 16);
    g_W[((size_t)nb * 320 + f) * 32 + l] = frag;
}

// ---------------- main persistent cluster kernel ----------------
__global__ void __launch_bounds__(256, 1) __cluster_dims__(2, 1, 1)
lstm_mma(const float* __restrict__ X, const float* __restrict__ bih,
         const float* __restrict__ bhh, const float* __restrict__ Wout,
         const float* __restrict__ bout, float* __restrict__ out) {
    extern __shared__ __align__(16) char smem[];
    const uint32_t sb = s2u(smem);
    const int tid = threadIdx.x, w = tid >> 5, l = tid & 31;
    const int gid = l >> 2, tid4 = l & 3;
    uint32_t jh;
    asm("mov.u32 %0, %%cluster_ctarank;" : "=r"(jh));
    const int pairIdx = blockIdx.x >> 1;
    const int n = pairIdx & 31, bh = pairIdx >> 5;

    // ---- load pre-fragmented weights (160 KB) ----
    {
        const uint4* src = g_W + (size_t)(n * 2 + (int)jh) * 320 * 32;
        uint4* dst = (uint4*)smem;
        for (int i = tid; i < 320 * 32; i += 256) dst[i] = src[i];
    }
    // ---- zero V buffers ----
    {
        uint32_t* v = (uint32_t*)(smem + V_OFF);
        for (int i = tid; i < 30720 / 4; i += 256) v[i] = 0;
    }
    // ---- biases for D1 init (per D-frag rows) ----
    float biasLo[2], biasHi[2];
    #pragma unroll
    for (int mtl = 0; mtl < 2; mtl++) {
        int r = (2 * w + mtl) * 16 + gid;
        int grow = (r >> 6) * 128 + (int)jh * 64 + (r & 63);
        biasLo[mtl] = bih[n * 512 + grow] + bhh[n * 512 + grow];
        int r2 = r + 8;
        grow = (r2 >> 6) * 128 + (int)jh * 64 + (r2 & 63);
        biasHi[mtl] = bih[n * 512 + grow] + bhh[n * 512 + grow];
    }
    // ---- update-role constants (thread owns jj0,jj0+1 x b0p,b0p+1) ----
    const int jj0 = 2 * l, b0p = 2 * w;
    const float wj0 = Wout[n * 128 + (int)jh * 64 + jj0];
    const float wj1 = Wout[n * 128 + (int)jh * 64 + jj0 + 1];
    const float bo = bout[n];
    float cst[2][2] = {{0.f, 0.f}, {0.f, 0.f}};
    float hst[2][2] = {{0.f, 0.f}, {0.f, 0.f}};
    // ---- x-role constants ----
    const int xp = (tid & 15) * 2;
    const int xb = bh * 16 + (tid >> 4);
    const uint32_t xoff = (uint32_t)((64 + (tid & 15)) * 24 + (tid >> 4)) * 4;
    // ---- cluster addresses ----
    const uint32_t peerBase = mapa_(sb, jh ^ 1u);
    const uint32_t r0Base = mapa_(sb, 0u);

    __syncthreads();
    // ---- x(0) into buffer 0 ----
    {
        float2 xv = *(const float2*)(X + ((size_t)xb * T_) * NS_ + xp);
        __nv_bfloat16 h0 = __float2bfloat16(xv.x), h1 = __float2bfloat16(xv.y);
        uint32_t xh = __bfloat16_as_ushort(h0) | ((uint32_t)__bfloat16_as_ushort(h1) << 16);
        uint32_t xl = __bfloat16_as_ushort(__float2bfloat16(xv.x - __bfloat162float(h0)))
                    | ((uint32_t)__bfloat16_as_ushort(__float2bfloat16(xv.y - __bfloat162float(h1))) << 16);
        *(uint32_t*)(smem + V_OFF + xoff) = xh;
        *(uint32_t*)(smem + V_OFF + xoff + 7680) = xl;
    }
    __syncthreads();
    CSYNC();

    float* sD = (float*)(smem + SD_OFF);
    float* sRed = (float*)(smem + SRED_OFF);
    const uint4* sWf = (const uint4*)smem;
    const uint32_t fb0 = (uint32_t)((2 * w) * 20) * 32 + l;
    const uint32_t fb1 = (uint32_t)((2 * w + 1) * 20) * 32 + l;

    for (int t = 0; t < T_; t++) {
        // ---- pred(t-1) from staged head partials (rank 0) ----
        if (jh == 0 && tid < 16 && t > 0) {
            int bf = (t - 1) & 1;
            float s = sRed[bf * 32 + tid] + sRed[bf * 32 + 16 + tid] + bo;
            out[((size_t)(bh * 16 + tid) * T_ + (t - 1)) * NS_ + n] = s;
        }
        // ---- x(t+1) prefetch ----
        float2 xv = make_float2(0.f, 0.f);
        if (t + 1 < T_) xv = *(const float2*)(X + ((size_t)xb * T_ + t + 1) * NS_ + xp);

        // ---- MMA phase: D[256x16] = W(hi/lo) * V(hi/lo), 3 terms ----
        float D1[2][2][4], D2[2][2][4];
        #pragma unroll
        for (int mtl = 0; mtl < 2; mtl++)
            #pragma unroll
            for (int ntl = 0; ntl < 2; ntl++) {
                D1[mtl][ntl][0] = biasLo[mtl]; D1[mtl][ntl][1] = biasLo[mtl];
                D1[mtl][ntl][2] = biasHi[mtl]; D1[mtl][ntl][3] = biasHi[mtl];
                D2[mtl][ntl][0] = 0.f; D2[mtl][ntl][1] = 0.f;
                D2[mtl][ntl][2] = 0.f; D2[mtl][ntl][3] = 0.f;
            }
        const uint32_t* svh = (const uint32_t*)(smem + V_OFF + (t & 1) * 15360);
        const uint32_t* svl = svh + 1920;
        #pragma unroll
        for (int kc = 0; kc < 10; kc++) {
            uint4 Ah0 = sWf[fb0 + kc * 32];
            uint4 Ah1 = sWf[fb1 + kc * 32];
            uint4 Al0 = sWf[fb0 + 320 + kc * 32];
            uint4 Al1 = sWf[fb1 + 320 + kc * 32];
            const int rB0 = (kc * 8 + tid4) * 24, rB1 = (kc * 8 + 4 + tid4) * 24;
            #pragma unroll
            for (int ntl = 0; ntl < 2; ntl++) {
                const int col = ntl * 8 + gid;
                uint32_t bh0 = svh[rB0 + col], bh1 = svh[rB1 + col];
                uint32_t bl0 = svl[rB0 + col], bl1 = svl[rB1 + col];
                MMA(D1[0][ntl], Ah0, bh0, bh1);
                MMA(D1[1][ntl], Ah1, bh0, bh1);
                MMA(D2[0][ntl], Ah0, bl0, bl1);
                MMA(D2[1][ntl], Ah1, bl0, bl1);
                MMA(D2[0][ntl], Al0, bh0, bh1);
                MMA(D2[1][ntl], Al1, bh0, bh1);
            }
        }
        // ---- stage D to smem ----
        #pragma unroll
        for (int mtl = 0; mtl < 2; mtl++)
            #pragma unroll
            for (int ntl = 0; ntl < 2; ntl++) {
                int row = (2 * w + mtl) * 16 + gid, colb = ntl * 8 + tid4 * 2;
                *(float2*)(sD + row * 18 + colb) =
                    make_float2(D1[mtl][ntl][0] + D2[mtl][ntl][0],
                                D1[mtl][ntl][1] + D2[mtl][ntl][1]);
                *(float2*)(sD + (row + 8) * 18 + colb) =
                    make_float2(D1[mtl][ntl][2] + D2[mtl][ntl][2],
                                D1[mtl][ntl][3] + D2[mtl][ntl][3]);
            }
        __syncthreads();
        // ---- epilogue: gather gates, update c/h, exchange h, head ----
        {
            float pp0 = 0.f, pp1 = 0.f;
            uint32_t hhi[2] = {0u, 0u}, hlo[2] = {0u, 0u};
            #pragma unroll
            for (int jq = 0; jq < 2; jq++) {
                const int jj = jj0 + jq;
                float2 i2 = *(const float2*)(sD + jj * 18 + b0p);
                float2 f2 = *(const float2*)(sD + (64 + jj) * 18 + b0p);
                float2 g2 = *(const float2*)(sD + (128 + jj) * 18 + b0p);
                float2 o2 = *(const float2*)(sD + (192 + jj) * 18 + b0p);
                const float wjq = jq ? wj1 : wj0;
                #pragma unroll
                for (int bq = 0; bq < 2; bq++) {
                    float iv = bq ? i2.y : i2.x;
                    float fv = bq ? f2.y : f2.x;
                    float gv = bq ? g2.y : g2.x;
                    float ov = bq ? o2.y : o2.x;
                    float cv = sigm_(fv) * cst[jq][bq] + sigm_(iv) * tanh_(gv);
                    cst[jq][bq] = cv;
                    float hv = sigm_(ov) * tanh_(cv);
                    hst[jq][bq] = hv;
                    if (bq) pp1 = fmaf(hv, wjq, pp1); else pp0 = fmaf(hv, wjq, pp0);
                    __nv_bfloat16 hb = __float2bfloat16(hv);
                    uint32_t hb16 = __bfloat16_as_ushort(hb);
                    uint32_t lb16 = __bfloat16_as_ushort(
                        __float2bfloat16(hv - __bfloat162float(hb)));
                    hhi[bq] |= hb16 << (16 * jq);
                    hlo[bq] |= lb16 << (16 * jq);
                }
            }
            // h(t+1) into next buffer, own + peer
            const uint32_t vbo = V_OFF + (uint32_t)(((t + 1) & 1) * 15360)
                               + (uint32_t)(((int)jh * 32 + l) * 24 + b0p) * 4;
            unsigned long long Hv = (unsigned long long)hhi[0] | ((unsigned long long)hhi[1] << 32);
            unsigned long long Lv = (unsigned long long)hlo[0] | ((unsigned long long)hlo[1] << 32);
            *(unsigned long long*)(smem + vbo) = Hv;
            *(unsigned long long*)(smem + vbo + 7680) = Lv;
            stc64(peerBase + vbo, Hv);
            stc64(peerBase + vbo + 7680, Lv);
            // x(t+1) into next buffer (local only)
            if (t + 1 < T_) {
                const uint32_t xo = V_OFF + (uint32_t)(((t + 1) & 1) * 15360) + xoff;
                __nv_bfloat16 h0 = __float2bfloat16(xv.x), h1 = __float2bfloat16(xv.y);
                uint32_t xh = __bfloat16_as_ushort(h0)
                            | ((uint32_t)__bfloat16_as_ushort(h1) << 16);
                uint32_t xl = __bfloat16_as_ushort(__float2bfloat16(xv.x - __bfloat162float(h0)))
                            | ((uint32_t)__bfloat16_as_ushort(__float2bfloat16(xv.y - __bfloat162float(h1))) << 16);
                *(uint32_t*)(smem + xo) = xh;
                *(uint32_t*)(smem + xo + 7680) = xl;
            }
            // head partials -> rank 0
            #pragma unroll
            for (int m = 1; m <= 16; m <<= 1) {
                pp0 += __shfl_xor_sync(0xffffffffu, pp0, m);
                pp1 += __shfl_xor_sync(0xffffffffu, pp1, m);
            }
            if (l == 0) {
                const uint32_t ro = SRED_OFF
                    + (uint32_t)((((t & 1) * 2 + (int)jh) * 16 + 2 * w) * 4);
                unsigned long long pv;
                asm("mov.b64 %0, {%1,%2};" : "=l"(pv) : "f"(pp0), "f"(pp1));
                stc64(r0Base + ro, pv);
            }
        }
        CSYNC();
    }
    // ---- pred(T-1) ----
    if (jh == 0 && tid < 16) {
        int bf = (T_ - 1) & 1;
        float s = sRed[bf * 32 + tid] + sRed[bf * 32 + 16 + tid] + bo;
        out[((size_t)(bh * 16 + tid) * T_ + (T_ - 1)) * NS_ + n] = s;
    }
    // ---- hT, cT ----
    {
        const size_t OB = (size_t)32 * T_ * NS_;
        const size_t OC = OB + (size_t)32 * 32 * 128;
        #pragma unroll
        for (int jq = 0; jq < 2; jq++)
            #pragma unroll
            for (int bq = 0; bq < 2; bq++) {
                int bgl = bh * 16 + b0p + bq;
                int jgl = (int)jh * 64 + jj0 + jq;
                out[OB + ((size_t)n * 32 + bgl) * 128 + jgl] = hst[jq][bq];
                out[OC + ((size_t)n * 32 + bgl) * 128 + jgl] = cst[jq][bq];
            }
    }
}

extern "C" void kernel_launch(void* const* d_in, const int* in_sizes, int n_in,
                              void* d_out, int out_size) {
    const float* X    = (const float*)d_in[0];
    const float* Wih  = (const float*)d_in[1];
    const float* Whh  = (const float*)d_in[2];
    const float* bih  = (const float*)d_in[3];
    const float* bhh  = (const float*)d_in[4];
    const float* Wout = (const float*)d_in[5];
    const float* bout = (const float*)d_in[6];

    prep_k<<<dim3(320, 64), 32>>>(Whh, Wih);

    cudaFuncSetAttribute(lstm_mma, cudaFuncAttributeMaxDynamicSharedMemorySize, SMEM_BYTES);
    lstm_mma<<<128, 256, SMEM_BYTES>>>(X, bih, bhh, Wout, bout, (float*)d_out);
}